// round 13
// baseline (speedup 1.0000x reference)
#include <cuda_runtime.h>
#include <cuda_bf16.h>
#include <cstdint>

#define BB 8
#define SS 50
#define II 20
#define CC 64
#define NN 4096
#define MAXM 1024

// ---------------- scratch (device globals; no allocs allowed) ----------------
__device__ float g_sums[BB * NN * CC];           // 8 MB segment sums (re-zeroed by k_rowcvt)
__device__ int   g_counts[BB * NN];              // re-zeroed by k_rowcvt
__device__ int   g_inv[BB * MAXM];               // slot -> (id | count<<12)
__device__ int   g_M[BB];
__device__ float g_h[NN];                        // emb[n] . proj_b
__device__ float2 g_part[16 * BB * NN];          // per-(mc,wm,b,n) partial (l, num)
// pre-swizzled bf16 operand arrays (SW128-style XOR within 128B rows)
__device__ __nv_bfloat16 g_ehi[NN * CC], g_elo[NN * CC];   // emb hi/lo
__device__ __nv_bfloat16 g_ghi[NN * CC], g_glo[NN * CC];   // (emb@W) hi/lo
__device__ __nv_bfloat16 g_chi[BB * MAXM * CC], g_clo[BB * MAXM * CC]; // cmean hi/lo

// swizzled element index for row r, channel c (64 bf16 = 128B rows)
__device__ __forceinline__ int swz(int r, int c) { return r * CC + (c ^ ((r & 7) << 3)); }

__device__ __forceinline__ uint32_t smem_u32(const void* p) {
    uint32_t a;
    asm("{ .reg .u64 t; cvta.to.shared.u64 t, %1; cvt.u32.u64 %0, t; }" : "=r"(a) : "l"(p));
    return a;
}
__device__ __forceinline__ void ldm4(uint32_t* r, uint32_t addr) {
    asm volatile("ldmatrix.sync.aligned.m8n8.x4.shared.b16 {%0,%1,%2,%3}, [%4];"
        : "=r"(r[0]), "=r"(r[1]), "=r"(r[2]), "=r"(r[3]) : "r"(addr));
}
__device__ __forceinline__ void mma16816(float* c, const uint32_t* a, uint32_t b0, uint32_t b1) {
    asm volatile("mma.sync.aligned.m16n8k16.row.col.f32.bf16.bf16.f32 "
        "{%0,%1,%2,%3}, {%4,%5,%6,%7}, {%8,%9}, {%0,%1,%2,%3};"
        : "+f"(c[0]), "+f"(c[1]), "+f"(c[2]), "+f"(c[3])
        : "r"(a[0]), "r"(a[1]), "r"(a[2]), "r"(a[3]), "r"(b0), "r"(b1));
}
#define CPA(dst, src)  asm volatile("cp.async.cg.shared.global [%0], [%1], 16;" :: "r"(dst), "l"(src))
#define CPCOMMIT()     asm volatile("cp.async.commit_group;" ::: "memory")
#define CPWAIT(n)      asm volatile("cp.async.wait_group %0;" :: "n"(n) : "memory")

// ---------------- K0: [blocks 0-255] gmat + e/g bf16 split + h  |  [256+] scatter ----------------
__global__ void k_prep_scatter(const float* __restrict__ emb, const float* __restrict__ W,
                               const float* __restrict__ pb, const float* __restrict__ x,
                               const int* __restrict__ ids, const int* __restrict__ slen) {
    __shared__ float Ws[CC * CC];
    __shared__ float Es[16 * CC];
    __shared__ float pbs[CC];
    int t = threadIdx.x;
    if (blockIdx.x >= 256) {
        // ---- masked scatter-add ----
        int g = (blockIdx.x - 256) * 256 + t;
        if (g >= BB * SS * II * CC) return;
        int c = g & (CC - 1);
        int e = g >> 6;
        int bs = e / II;
        int s = bs % SS;
        int b = bs / SS;
        if (s < slen[b]) {
            int id = ids[e];
            atomicAdd(&g_sums[(((size_t)b * NN + id) << 6) + c], x[g]);
            if (c == 0) atomicAdd(&g_counts[b * NN + id], 1);
        }
        return;
    }
    {
        const float4* W4 = reinterpret_cast<const float4*>(W);
        float4* Ws4 = reinterpret_cast<float4*>(Ws);
        for (int k = t; k < 1024; k += 256) Ws4[k] = W4[k];
        const float4* E4 = reinterpret_cast<const float4*>(emb + (size_t)blockIdx.x * 16 * CC);
        reinterpret_cast<float4*>(Es)[t] = E4[t];
        if (t < CC) pbs[t] = pb[t];
    }
    __syncthreads();
    int nbase = blockIdx.x * 16;
    int c = t & (CC - 1);
    int rg = t >> 6;
#pragma unroll
    for (int it = 0; it < 4; it++) {
        int r = it * 4 + rg;
        float a0 = 0.0f, a1 = 0.0f;
#pragma unroll
        for (int cp = 0; cp < CC; cp += 2) {
            a0 = fmaf(Es[r * CC + cp],     Ws[cp * CC + c],       a0);
            a1 = fmaf(Es[r * CC + cp + 1], Ws[(cp + 1) * CC + c], a1);
        }
        float gv = a0 + a1;
        float ev = Es[r * CC + c];
        int si = swz(nbase + r, c);
        __nv_bfloat16 eh = __float2bfloat16(ev);
        __nv_bfloat16 el = __float2bfloat16(ev - __bfloat162float(eh));
        __nv_bfloat16 gh = __float2bfloat16(gv);
        __nv_bfloat16 gl = __float2bfloat16(gv - __bfloat162float(gh));
        g_ehi[si] = eh; g_elo[si] = el;
        g_ghi[si] = gh; g_glo[si] = gl;
    }
    if (t < 16) {
        float h = 0.0f;
#pragma unroll
        for (int cc = 0; cc < CC; cc++) h = fmaf(Es[t * CC + cc], pbs[cc], h);
        g_h[nbase + t] = h;
    }
}

// ---------------- K2a: slot assignment; writes inverse map slot -> (id|cnt<<12) ----------------
__global__ void k_slots() {
    __shared__ int wsum[32];
    int b = blockIdx.x;
    int t = threadIdx.x;          // 1024 threads, 4 ids each
    int base = b * NN;
    int cnts[4], flags[4];
    int local = 0;
#pragma unroll
    for (int j = 0; j < 4; j++) {
        cnts[j] = g_counts[base + t * 4 + j];
        flags[j] = (cnts[j] > 0);
        local += flags[j];
    }
    int lane = t & 31, wid = t >> 5;
    int v = local;
#pragma unroll
    for (int off = 1; off < 32; off <<= 1) {
        int u = __shfl_up_sync(0xffffffffu, v, off);
        if (lane >= off) v += u;
    }
    if (lane == 31) wsum[wid] = v;
    __syncthreads();
    if (wid == 0) {
        int w = wsum[lane];
#pragma unroll
        for (int off = 1; off < 32; off <<= 1) {
            int u = __shfl_up_sync(0xffffffffu, w, off);
            if (lane >= off) w += u;
        }
        wsum[lane] = w;
    }
    __syncthreads();
    int warpBase = (wid == 0) ? 0 : wsum[wid - 1];
    int excl = warpBase + v - local;
#pragma unroll
    for (int j = 0; j < 4; j++) {
        if (flags[j]) g_inv[b * MAXM + (excl++)] = (t * 4 + j) | (cnts[j] << 12);
    }
    if (t == 0) g_M[b] = wsum[31];
}

// ---------------- K2b: warp-per-slot: mean + bf16 split + re-zero ----------------
__global__ void k_rowcvt() {
    int w = blockIdx.x * 8 + (threadIdx.x >> 5);   // slot index over BB*MAXM
    int lane = threadIdx.x & 31;
    int b = w >> 10;
    int slot = w & (MAXM - 1);
    if (slot >= g_M[b]) return;
    int packed = g_inv[w];
    int id = packed & 4095;
    float inv = 1.0f / (float)(packed >> 12);
    int src = b * NN + id;
    float2* srow = reinterpret_cast<float2*>(g_sums + ((size_t)src << 6));
    float2 v = srow[lane];
    v.x *= inv; v.y *= inv;
    __nv_bfloat16 h0 = __float2bfloat16(v.x);
    __nv_bfloat16 l0 = __float2bfloat16(v.x - __bfloat162float(h0));
    __nv_bfloat16 h1 = __float2bfloat16(v.y);
    __nv_bfloat16 l1 = __float2bfloat16(v.y - __bfloat162float(h1));
    uint32_t hp = (uint32_t)__bfloat16_as_ushort(h0) | ((uint32_t)__bfloat16_as_ushort(h1) << 16);
    uint32_t lp = (uint32_t)__bfloat16_as_ushort(l0) | ((uint32_t)__bfloat16_as_ushort(l1) << 16);
    int row = b * MAXM + slot;
    int ui = row * 32 + (((lane * 2) ^ ((row & 7) << 3)) >> 1);
    reinterpret_cast<uint32_t*>(g_chi)[ui] = hp;
    reinterpret_cast<uint32_t*>(g_clo)[ui] = lp;
    srow[lane] = make_float2(0.0f, 0.0f);          // restore invariant
    if (lane == 0) g_counts[src] = 0;
}

// ---------------- K3: tile kernel, (mc, b, nt), 2 pipelined 64-m subtiles ----------------
// smem: 0 EHI | 8192 ELO | 16384 GHI | 24576 GLO | 32768 + buf*16384: {CHI, CLO}
#define SM_CBUF 32768
#define SM_TOTAL 65536

__global__ void __launch_bounds__(256, 2) k_mma() {
    extern __shared__ __align__(1024) char smem[];
    int t = threadIdx.x;
    int bid = blockIdx.x;
    int nt = bid & 63;
    int b  = (bid >> 6) & 7;
    int mc = bid >> 9;
    int M = g_M[b];
    int m0 = mc * 128;
    if (m0 >= M) return;
    int nsub = min(2, (M - m0 + 63) >> 6);
    uint32_t sb = smem_u32(smem);

    // ---- stage A (e/g) once + B subtiles via cp.async ----
    {
        int arow = nt * 512;                       // uint4 offset: 64 rows * 8
        const uint4* s_eh = reinterpret_cast<const uint4*>(g_ehi) + arow;
        const uint4* s_el = reinterpret_cast<const uint4*>(g_elo) + arow;
        const uint4* s_gh = reinterpret_cast<const uint4*>(g_ghi) + arow;
        const uint4* s_gl = reinterpret_cast<const uint4*>(g_glo) + arow;
        for (int k = t; k < 512; k += 256) {
            CPA(sb + k * 16,         s_eh + k);
            CPA(sb + 8192 + k * 16,  s_el + k);
            CPA(sb + 16384 + k * 16, s_gh + k);
            CPA(sb + 24576 + k * 16, s_gl + k);
        }
    }
#pragma unroll 1
    for (int s = 0; s < nsub; s++) {
        int mE = min(64, M - (m0 + s * 64));
        int cnt = mE * 8;
        size_t g = ((size_t)(b * MAXM + m0 + s * 64)) * 8;
        const uint4* sh = reinterpret_cast<const uint4*>(g_chi) + g;
        const uint4* sl = reinterpret_cast<const uint4*>(g_clo) + g;
        uint32_t dst = sb + SM_CBUF + s * 16384;
        for (int k = t; k < cnt; k += 256) {
            CPA(dst + k * 16, sh + k);
            CPA(dst + 8192 + k * 16, sl + k);
        }
        CPCOMMIT();
    }

    int lane = t & 31, wid = t >> 5;
    int wn = wid & 3, wm = wid >> 2;
    int mat = lane >> 3, rw = lane & 7;

    int rowA = wn * 16 + ((mat & 1) << 3) + rw;
    uint32_t xA = (uint32_t)(rowA * 128 + ((rowA & 7) << 4));
    int cgA = mat >> 1;
    int rowB = wm * 32 + ((mat >> 1) << 3) + rw;
    uint32_t xB0 = (uint32_t)(rowB * 128 + ((rowB & 7) << 4));
    uint32_t xB1 = xB0 + 16 * 128;
    int cgB = mat & 1;

    float l1 = 0.0f, v1 = 0.0f, l2 = 0.0f, v2 = 0.0f;

#pragma unroll 1
    for (int s = 0; s < nsub; s++) {
        if (s == 0) { if (nsub == 2) { CPWAIT(1); } else { CPWAIT(0); } }
        else { CPWAIT(0); }
        __syncthreads();

        uint32_t cb = sb + SM_CBUF + s * 16384;   // CHI base; CLO = +8192
        float aS[4][4], aT[4][4];
#pragma unroll
        for (int f = 0; f < 4; f++)
#pragma unroll
            for (int j = 0; j < 4; j++) { aS[f][j] = 0.0f; aT[f][j] = 0.0f; }

#pragma unroll
        for (int k16 = 0; k16 < 4; k16++) {
            uint32_t cA = (uint32_t)((2 * k16 + cgA) << 4);
            uint32_t cB = (uint32_t)((2 * k16 + cgB) << 4);
            uint32_t aeh[4], ael[4], agh[4], agl[4];
            ldm4(aeh, sb + 0     + (xA ^ cA));
            ldm4(ael, sb + 8192  + (xA ^ cA));
            ldm4(agh, sb + 16384 + (xA ^ cA));
            ldm4(agl, sb + 24576 + (xA ^ cA));
#pragma unroll
            for (int g2 = 0; g2 < 2; g2++) {
                uint32_t xb = (g2 ? xB1 : xB0);
                uint32_t bh[4], bl[4];
                ldm4(bh, cb + (xb ^ cB));
                ldm4(bl, cb + 8192 + (xb ^ cB));
                // round-robin over 4 independent accumulators (dep distance 4)
                mma16816(aS[2 * g2],     aeh, bh[0], bh[1]);
                mma16816(aS[2 * g2 + 1], aeh, bh[2], bh[3]);
                mma16816(aT[2 * g2],     agh, bh[0], bh[1]);
                mma16816(aT[2 * g2 + 1], agh, bh[2], bh[3]);
                mma16816(aS[2 * g2],     aeh, bl[0], bl[1]);
                mma16816(aS[2 * g2 + 1], aeh, bl[2], bl[3]);
                mma16816(aT[2 * g2],     agh, bl[0], bl[1]);
                mma16816(aT[2 * g2 + 1], agh, bl[2], bl[3]);
                mma16816(aS[2 * g2],     ael, bh[0], bh[1]);
                mma16816(aS[2 * g2 + 1], ael, bh[2], bh[3]);
                mma16816(aT[2 * g2],     agl, bh[0], bh[1]);
                mma16816(aT[2 * g2 + 1], agl, bh[2], bh[3]);
            }
        }

        int mEnd = min(64, M - (m0 + s * 64));
#pragma unroll
        for (int f = 0; f < 4; f++) {
            int mloc = wm * 32 + f * 8 + ((lane & 3) << 1);
#pragma unroll
            for (int j = 0; j < 2; j++) {
                if (mloc + j < mEnd) {
                    float sc = aS[f][j];
                    sc = fmaxf(sc, 0.0f) + 0.2f * fminf(sc, 0.0f);
                    float e = __expf(sc);
                    l1 += e; v1 = fmaf(e, aT[f][j], v1);
                    float s2 = aS[f][j + 2];
                    s2 = fmaxf(s2, 0.0f) + 0.2f * fminf(s2, 0.0f);
                    float e2 = __expf(s2);
                    l2 += e2; v2 = fmaf(e2, aT[f][j + 2], v2);
                }
            }
        }
        if (s + 1 < nsub) __syncthreads();
    }

    // ---- reduce within quad, write per-(mc,wm) partial directly ----
#pragma unroll
    for (int off = 1; off < 4; off <<= 1) {
        l1 += __shfl_xor_sync(0xffffffffu, l1, off);
        v1 += __shfl_xor_sync(0xffffffffu, v1, off);
        l2 += __shfl_xor_sync(0xffffffffu, l2, off);
        v2 += __shfl_xor_sync(0xffffffffu, v2, off);
    }
    if ((lane & 3) == 0) {
        int n0 = nt * 64 + wn * 16 + (lane >> 2);
        size_t base = ((size_t)(mc * 2 + wm) * BB + b) * NN + n0;
        g_part[base]     = make_float2(l1, v1);
        g_part[base + 8] = make_float2(l2, v2);
    }
}

// ---------------- K4: finalize: sum valid (mc, wm) partials ----------------
__global__ void k_final(float* __restrict__ out) {
    int i = blockIdx.x * 256 + threadIdx.x;        // i = b*NN + n
    int b = i >> 12;
    int n = i & (NN - 1);
    int nh = ((g_M[b] + 127) >> 7) * 2;            // 2 wm halves per m-chunk
    float l = 0.0f, v = 0.0f;
    for (int h = 0; h < nh; h++) {
        float2 p = g_part[((size_t)h * BB + b) * NN + n];
        l += p.x; v += p.y;
    }
    out[i] = v / l + g_h[n];
}

extern "C" void kernel_launch(void* const* d_in, const int* in_sizes, int n_in,
                              void* d_out, int out_size) {
    const float* x    = (const float*)d_in[0];
    const float* emb  = (const float*)d_in[1];
    const float* W    = (const float*)d_in[2];
    const float* pb   = (const float*)d_in[3];
    const int*   ids  = (const int*)d_in[4];
    const int*   slen = (const int*)d_in[5];
    float* out = (float*)d_out;

    cudaFuncSetAttribute(k_mma, cudaFuncAttributeMaxDynamicSharedMemorySize, SM_TOTAL);

    int scat_blocks = (BB * SS * II * CC + 255) / 256;
    k_prep_scatter<<<256 + scat_blocks, 256>>>(emb, W, pb, x, ids, slen);
    k_slots<<<BB, 1024>>>();
    k_rowcvt<<<BB * MAXM / 8, 256>>>();
    k_mma<<<8 * BB * 64, 256, SM_TOTAL>>>();
    k_final<<<(BB * NN) / 256, 256>>>(out);
}

// round 14
// speedup vs baseline: 1.0406x; 1.0406x over previous
#include <cuda_runtime.h>
#include <cuda_bf16.h>
#include <cstdint>

#define BB 8
#define SS 50
#define II 20
#define CC 64
#define NN 4096
#define MAXM 1024

// ---------------- scratch (device globals; no allocs allowed) ----------------
__device__ float g_sums[BB * NN * CC];           // 8 MB segment sums (re-zeroed by k_rowcvt)
__device__ int   g_counts[BB * NN];              // re-zeroed by k_rowcvt
__device__ int   g_inv[BB * MAXM];               // slot -> (id | count<<12)
__device__ int   g_M[BB];
__device__ float g_h[NN];                        // emb[n] . proj_b
__device__ float2 g_part[16 * BB * NN];          // per-(mc,wm,b,n) partial (l, num)
// pre-swizzled bf16 operand arrays (SW128-style XOR within 128B rows)
__device__ __nv_bfloat16 g_ehi[NN * CC], g_elo[NN * CC];   // emb hi/lo
__device__ __nv_bfloat16 g_ghi[NN * CC], g_glo[NN * CC];   // (emb@W) hi/lo
__device__ __nv_bfloat16 g_chi[BB * MAXM * CC], g_clo[BB * MAXM * CC]; // cmean hi/lo

// swizzled element index for row r, channel c (64 bf16 = 128B rows)
__device__ __forceinline__ int swz(int r, int c) { return r * CC + (c ^ ((r & 7) << 3)); }

__device__ __forceinline__ uint32_t smem_u32(const void* p) {
    uint32_t a;
    asm("{ .reg .u64 t; cvta.to.shared.u64 t, %1; cvt.u32.u64 %0, t; }" : "=r"(a) : "l"(p));
    return a;
}
__device__ __forceinline__ void ldm4(uint32_t* r, uint32_t addr) {
    asm volatile("ldmatrix.sync.aligned.m8n8.x4.shared.b16 {%0,%1,%2,%3}, [%4];"
        : "=r"(r[0]), "=r"(r[1]), "=r"(r[2]), "=r"(r[3]) : "r"(addr));
}
__device__ __forceinline__ void mma16816(float* c, const uint32_t* a, uint32_t b0, uint32_t b1) {
    asm volatile("mma.sync.aligned.m16n8k16.row.col.f32.bf16.bf16.f32 "
        "{%0,%1,%2,%3}, {%4,%5,%6,%7}, {%8,%9}, {%0,%1,%2,%3};"
        : "+f"(c[0]), "+f"(c[1]), "+f"(c[2]), "+f"(c[3])
        : "r"(a[0]), "r"(a[1]), "r"(a[2]), "r"(a[3]), "r"(b0), "r"(b1));
}
#define CPA(dst, src)  asm volatile("cp.async.cg.shared.global [%0], [%1], 16;" :: "r"(dst), "l"(src))
#define CPCOMMIT()     asm volatile("cp.async.commit_group;" ::: "memory")
#define CPWAIT(n)      asm volatile("cp.async.wait_group %0;" :: "n"(n) : "memory")

// ---------------- K0: [blocks 0-255] gmat + e/g bf16 split + h  |  [256+] scatter ----------------
__global__ void k_prep_scatter(const float* __restrict__ emb, const float* __restrict__ W,
                               const float* __restrict__ pb, const float* __restrict__ x,
                               const int* __restrict__ ids, const int* __restrict__ slen) {
    __shared__ float Ws[CC * CC];
    __shared__ float Es[16 * CC];
    __shared__ float pbs[CC];
    int t = threadIdx.x;
    if (blockIdx.x >= 256) {
        // ---- masked scatter-add ----
        int g = (blockIdx.x - 256) * 256 + t;
        if (g >= BB * SS * II * CC) return;
        int c = g & (CC - 1);
        int e = g >> 6;
        int bs = e / II;
        int s = bs % SS;
        int b = bs / SS;
        if (s < slen[b]) {
            int id = ids[e];
            atomicAdd(&g_sums[(((size_t)b * NN + id) << 6) + c], x[g]);
            if (c == 0) atomicAdd(&g_counts[b * NN + id], 1);
        }
        return;
    }
    {
        const float4* W4 = reinterpret_cast<const float4*>(W);
        float4* Ws4 = reinterpret_cast<float4*>(Ws);
        for (int k = t; k < 1024; k += 256) Ws4[k] = W4[k];
        const float4* E4 = reinterpret_cast<const float4*>(emb + (size_t)blockIdx.x * 16 * CC);
        reinterpret_cast<float4*>(Es)[t] = E4[t];
        if (t < CC) pbs[t] = pb[t];
    }
    __syncthreads();
    int nbase = blockIdx.x * 16;
    int c = t & (CC - 1);
    int rg = t >> 6;
#pragma unroll
    for (int it = 0; it < 4; it++) {
        int r = it * 4 + rg;
        float a0 = 0.0f, a1 = 0.0f;
#pragma unroll
        for (int cp = 0; cp < CC; cp += 2) {
            a0 = fmaf(Es[r * CC + cp],     Ws[cp * CC + c],       a0);
            a1 = fmaf(Es[r * CC + cp + 1], Ws[(cp + 1) * CC + c], a1);
        }
        float gv = a0 + a1;
        float ev = Es[r * CC + c];
        int si = swz(nbase + r, c);
        __nv_bfloat16 eh = __float2bfloat16(ev);
        __nv_bfloat16 el = __float2bfloat16(ev - __bfloat162float(eh));
        __nv_bfloat16 gh = __float2bfloat16(gv);
        __nv_bfloat16 gl = __float2bfloat16(gv - __bfloat162float(gh));
        g_ehi[si] = eh; g_elo[si] = el;
        g_ghi[si] = gh; g_glo[si] = gl;
    }
    if (t < 16) {
        float h = 0.0f;
#pragma unroll
        for (int cc = 0; cc < CC; cc++) h = fmaf(Es[t * CC + cc], pbs[cc], h);
        g_h[nbase + t] = h;
    }
}

// ---------------- K2a: slot assignment; writes inverse map slot -> (id|cnt<<12) ----------------
__global__ void k_slots() {
    __shared__ int wsum[32];
    int b = blockIdx.x;
    int t = threadIdx.x;          // 1024 threads, 4 ids each
    int base = b * NN;
    int cnts[4], flags[4];
    int local = 0;
#pragma unroll
    for (int j = 0; j < 4; j++) {
        cnts[j] = g_counts[base + t * 4 + j];
        flags[j] = (cnts[j] > 0);
        local += flags[j];
    }
    int lane = t & 31, wid = t >> 5;
    int v = local;
#pragma unroll
    for (int off = 1; off < 32; off <<= 1) {
        int u = __shfl_up_sync(0xffffffffu, v, off);
        if (lane >= off) v += u;
    }
    if (lane == 31) wsum[wid] = v;
    __syncthreads();
    if (wid == 0) {
        int w = wsum[lane];
#pragma unroll
        for (int off = 1; off < 32; off <<= 1) {
            int u = __shfl_up_sync(0xffffffffu, w, off);
            if (lane >= off) w += u;
        }
        wsum[lane] = w;
    }
    __syncthreads();
    int warpBase = (wid == 0) ? 0 : wsum[wid - 1];
    int excl = warpBase + v - local;
#pragma unroll
    for (int j = 0; j < 4; j++) {
        if (flags[j]) g_inv[b * MAXM + (excl++)] = (t * 4 + j) | (cnts[j] << 12);
    }
    if (t == 0) g_M[b] = wsum[31];
}

// ---------------- K2b: warp-per-slot: mean + bf16 split + re-zero ----------------
__global__ void k_rowcvt() {
    int w = blockIdx.x * 8 + (threadIdx.x >> 5);   // slot index over BB*MAXM
    int lane = threadIdx.x & 31;
    int b = w >> 10;
    int slot = w & (MAXM - 1);
    if (slot >= g_M[b]) return;
    int packed = g_inv[w];
    int id = packed & 4095;
    float inv = 1.0f / (float)(packed >> 12);
    int src = b * NN + id;
    float2* srow = reinterpret_cast<float2*>(g_sums + ((size_t)src << 6));
    float2 v = srow[lane];
    v.x *= inv; v.y *= inv;
    __nv_bfloat16 h0 = __float2bfloat16(v.x);
    __nv_bfloat16 l0 = __float2bfloat16(v.x - __bfloat162float(h0));
    __nv_bfloat16 h1 = __float2bfloat16(v.y);
    __nv_bfloat16 l1 = __float2bfloat16(v.y - __bfloat162float(h1));
    uint32_t hp = (uint32_t)__bfloat16_as_ushort(h0) | ((uint32_t)__bfloat16_as_ushort(h1) << 16);
    uint32_t lp = (uint32_t)__bfloat16_as_ushort(l0) | ((uint32_t)__bfloat16_as_ushort(l1) << 16);
    int row = b * MAXM + slot;
    int ui = row * 32 + (((lane * 2) ^ ((row & 7) << 3)) >> 1);
    reinterpret_cast<uint32_t*>(g_chi)[ui] = hp;
    reinterpret_cast<uint32_t*>(g_clo)[ui] = lp;
    srow[lane] = make_float2(0.0f, 0.0f);          // restore invariant
    if (lane == 0) g_counts[src] = 0;
}

// ---------------- K3: tile kernel, (mc=256m, b, nt), 4 subtiles, 3-deep pipeline ----------------
// smem: 0 EHI | 8192 ELO | 16384 GHI | 24576 GLO | 32768 + buf*16384: {CHI, CLO} x3
#define SM_CBUF 32768
#define SM_TOTAL (32768 + 3 * 16384)

__device__ __forceinline__ void cp_csub(uint32_t sb, int b, int m0, int buf, int t, int M) {
    int mE = min(64, M - m0);
    int cnt = mE * 8;
    size_t g = ((size_t)(b * MAXM + m0)) * 8;
    const uint4* sh = reinterpret_cast<const uint4*>(g_chi) + g;
    const uint4* sl = reinterpret_cast<const uint4*>(g_clo) + g;
    uint32_t dst = sb + SM_CBUF + buf * 16384;
    for (int k = t; k < cnt; k += 256) {
        CPA(dst + k * 16, sh + k);
        CPA(dst + 8192 + k * 16, sl + k);
    }
}

__global__ void __launch_bounds__(256, 2) k_mma() {
    extern __shared__ __align__(1024) char smem[];
    int t = threadIdx.x;
    int bid = blockIdx.x;
    int nt = bid & 63;
    int b  = (bid >> 6) & 7;
    int mc = bid >> 9;
    int M = g_M[b];
    int m0 = mc * 256;
    if (m0 >= M) return;
    int nsub = min(4, (M - m0 + 63) >> 6);
    uint32_t sb = smem_u32(smem);

    // ---- group0: A (e/g) + C0; group1: C1 ----
    {
        int arow = nt * 512;                       // uint4 offset: 64 rows * 8
        const uint4* s_eh = reinterpret_cast<const uint4*>(g_ehi) + arow;
        const uint4* s_el = reinterpret_cast<const uint4*>(g_elo) + arow;
        const uint4* s_gh = reinterpret_cast<const uint4*>(g_ghi) + arow;
        const uint4* s_gl = reinterpret_cast<const uint4*>(g_glo) + arow;
        for (int k = t; k < 512; k += 256) {
            CPA(sb + k * 16,         s_eh + k);
            CPA(sb + 8192 + k * 16,  s_el + k);
            CPA(sb + 16384 + k * 16, s_gh + k);
            CPA(sb + 24576 + k * 16, s_gl + k);
        }
    }
    cp_csub(sb, b, m0, 0, t, M);
    CPCOMMIT();
    if (nsub > 1) { cp_csub(sb, b, m0 + 64, 1, t, M); CPCOMMIT(); }

    int lane = t & 31, wid = t >> 5;
    int wn = wid & 3, wm = wid >> 2;
    int mat = lane >> 3, rw = lane & 7;

    int rowA = wn * 16 + ((mat & 1) << 3) + rw;
    uint32_t xA = (uint32_t)(rowA * 128 + ((rowA & 7) << 4));
    int cgA = mat >> 1;
    int rowB = wm * 32 + ((mat >> 1) << 3) + rw;
    uint32_t xB0 = (uint32_t)(rowB * 128 + ((rowB & 7) << 4));
    uint32_t xB1 = xB0 + 16 * 128;
    int cgB = mat & 1;

    float l1 = 0.0f, v1 = 0.0f, l2 = 0.0f, v2 = 0.0f;

#pragma unroll 1
    for (int s = 0; s < nsub; s++) {
        if (s + 2 < nsub) { cp_csub(sb, b, m0 + (s + 2) * 64, (s + 2) % 3, t, M); CPCOMMIT(); }
        // pending groups allowed after wait = min(2, nsub-1-s)
        int rem = nsub - 1 - s;
        if (rem >= 2) { CPWAIT(2); } else if (rem == 1) { CPWAIT(1); } else { CPWAIT(0); }
        __syncthreads();

        uint32_t cb = sb + SM_CBUF + (s % 3) * 16384;   // CHI base; CLO = +8192
        float aS[4][4], aT[4][4];
#pragma unroll
        for (int f = 0; f < 4; f++)
#pragma unroll
            for (int j = 0; j < 4; j++) { aS[f][j] = 0.0f; aT[f][j] = 0.0f; }

#pragma unroll
        for (int k16 = 0; k16 < 4; k16++) {
            uint32_t cA = (uint32_t)((2 * k16 + cgA) << 4);
            uint32_t cB = (uint32_t)((2 * k16 + cgB) << 4);
            uint32_t aeh[4], ael[4], agh[4], agl[4];
            ldm4(aeh, sb + 0     + (xA ^ cA));
            ldm4(ael, sb + 8192  + (xA ^ cA));
            ldm4(agh, sb + 16384 + (xA ^ cA));
            ldm4(agl, sb + 24576 + (xA ^ cA));
#pragma unroll
            for (int g2 = 0; g2 < 2; g2++) {
                uint32_t xb = (g2 ? xB1 : xB0);
                uint32_t bh[4], bl[4];
                ldm4(bh, cb + (xb ^ cB));
                ldm4(bl, cb + 8192 + (xb ^ cB));
                mma16816(aS[2 * g2],     aeh, bh[0], bh[1]);
                mma16816(aS[2 * g2 + 1], aeh, bh[2], bh[3]);
                mma16816(aT[2 * g2],     agh, bh[0], bh[1]);
                mma16816(aT[2 * g2 + 1], agh, bh[2], bh[3]);
                mma16816(aS[2 * g2],     aeh, bl[0], bl[1]);
                mma16816(aS[2 * g2 + 1], aeh, bl[2], bl[3]);
                mma16816(aT[2 * g2],     agh, bl[0], bl[1]);
                mma16816(aT[2 * g2 + 1], agh, bl[2], bl[3]);
                mma16816(aS[2 * g2],     ael, bh[0], bh[1]);
                mma16816(aS[2 * g2 + 1], ael, bh[2], bh[3]);
                mma16816(aT[2 * g2],     agl, bh[0], bh[1]);
                mma16816(aT[2 * g2 + 1], agl, bh[2], bh[3]);
            }
        }

        int mEnd = min(64, M - (m0 + s * 64));
#pragma unroll
        for (int f = 0; f < 4; f++) {
            int mloc = wm * 32 + f * 8 + ((lane & 3) << 1);
#pragma unroll
            for (int j = 0; j < 2; j++) {
                if (mloc + j < mEnd) {
                    float sc = aS[f][j];
                    sc = fmaxf(sc, 0.0f) + 0.2f * fminf(sc, 0.0f);
                    float e = __expf(sc);
                    l1 += e; v1 = fmaf(e, aT[f][j], v1);
                    float s2 = aS[f][j + 2];
                    s2 = fmaxf(s2, 0.0f) + 0.2f * fminf(s2, 0.0f);
                    float e2 = __expf(s2);
                    l2 += e2; v2 = fmaf(e2, aT[f][j + 2], v2);
                }
            }
        }
        if (s + 1 < nsub) __syncthreads();
    }

    // ---- reduce within quad, write per-(mc,wm) partial directly ----
#pragma unroll
    for (int off = 1; off < 4; off <<= 1) {
        l1 += __shfl_xor_sync(0xffffffffu, l1, off);
        v1 += __shfl_xor_sync(0xffffffffu, v1, off);
        l2 += __shfl_xor_sync(0xffffffffu, l2, off);
        v2 += __shfl_xor_sync(0xffffffffu, v2, off);
    }
    if ((lane & 3) == 0) {
        int n0 = nt * 64 + wn * 16 + (lane >> 2);
        size_t base = ((size_t)(mc * 2 + wm) * BB + b) * NN + n0;
        g_part[base]     = make_float2(l1, v1);
        g_part[base + 8] = make_float2(l2, v2);
    }
}

// ---------------- K4: finalize: sum valid (mc, wm) partials ----------------
__global__ void k_final(float* __restrict__ out) {
    int i = blockIdx.x * 256 + threadIdx.x;        // i = b*NN + n
    int b = i >> 12;
    int n = i & (NN - 1);
    int nh = ((g_M[b] + 255) >> 8) * 2;            // 2 wm halves per 256-m chunk
    float l = 0.0f, v = 0.0f;
    for (int h = 0; h < nh; h++) {
        float2 p = g_part[((size_t)h * BB + b) * NN + n];
        l += p.x; v += p.y;
    }
    out[i] = v / l + g_h[n];
}

extern "C" void kernel_launch(void* const* d_in, const int* in_sizes, int n_in,
                              void* d_out, int out_size) {
    const float* x    = (const float*)d_in[0];
    const float* emb  = (const float*)d_in[1];
    const float* W    = (const float*)d_in[2];
    const float* pb   = (const float*)d_in[3];
    const int*   ids  = (const int*)d_in[4];
    const int*   slen = (const int*)d_in[5];
    float* out = (float*)d_out;

    cudaFuncSetAttribute(k_mma, cudaFuncAttributeMaxDynamicSharedMemorySize, SM_TOTAL);

    int scat_blocks = (BB * SS * II * CC + 255) / 256;
    k_prep_scatter<<<256 + scat_blocks, 256>>>(emb, W, pb, x, ids, slen);
    k_slots<<<BB, 1024>>>();
    k_rowcvt<<<BB * MAXM / 8, 256>>>();
    k_mma<<<4 * BB * 64, 256, SM_TOTAL>>>();
    k_final<<<(BB * NN) / 256, 256>>>(out);
}

// round 17
// speedup vs baseline: 1.3066x; 1.2557x over previous
#include <cuda_runtime.h>
#include <cuda_fp16.h>
#include <cstdint>

#define BB 8
#define SS 50
#define II 20
#define CC 64
#define NN 4096
#define MAXM 1024

// ---------------- scratch (device globals; no allocs allowed) ----------------
__device__ float g_sums[BB * NN * CC];           // 8 MB segment sums (re-zeroed by k_rowcvt)
__device__ int   g_counts[BB * NN];              // re-zeroed by k_rowcvt
__device__ int   g_inv[BB * MAXM];               // slot -> (id | count<<12)
__device__ int   g_M[BB];
__device__ float g_h[NN];                        // emb[n] . proj_b
__device__ float2 g_part[16 * BB * NN];          // per-(mc,wm,b,n) partial (l, num)
// pre-swizzled fp16 operand arrays (SW128-style XOR within 128B rows)
__device__ __half g_eh[NN * CC];                 // emb (fp16 hi)
__device__ __half g_gh[NN * CC], g_gl[NN * CC];  // (emb@W) hi/lo fp16 split
__device__ __half g_ch[BB * MAXM * CC];          // cmean fp16

// swizzled element index for row r, channel c (64 fp16 = 128B rows)
__device__ __forceinline__ int swz(int r, int c) { return r * CC + (c ^ ((r & 7) << 3)); }

__device__ __forceinline__ uint32_t smem_u32(const void* p) {
    uint32_t a;
    asm("{ .reg .u64 t; cvta.to.shared.u64 t, %1; cvt.u32.u64 %0, t; }" : "=r"(a) : "l"(p));
    return a;
}
__device__ __forceinline__ void ldm4(uint32_t* r, uint32_t addr) {
    asm volatile("ldmatrix.sync.aligned.m8n8.x4.shared.b16 {%0,%1,%2,%3}, [%4];"
        : "=r"(r[0]), "=r"(r[1]), "=r"(r[2]), "=r"(r[3]) : "r"(addr));
}
__device__ __forceinline__ void mma16816(float* c, const uint32_t* a, uint32_t b0, uint32_t b1) {
    asm volatile("mma.sync.aligned.m16n8k16.row.col.f32.f16.f16.f32 "
        "{%0,%1,%2,%3}, {%4,%5,%6,%7}, {%8,%9}, {%0,%1,%2,%3};"
        : "+f"(c[0]), "+f"(c[1]), "+f"(c[2]), "+f"(c[3])
        : "r"(a[0]), "r"(a[1]), "r"(a[2]), "r"(a[3]), "r"(b0), "r"(b1));
}
#define CPA(dst, src)  asm volatile("cp.async.cg.shared.global [%0], [%1], 16;" :: "r"(dst), "l"(src))
#define CPCOMMIT()     asm volatile("cp.async.commit_group;" ::: "memory")
#define CPWAIT(n)      asm volatile("cp.async.wait_group %0;" :: "n"(n) : "memory")

// ---------------- K0: [blocks 0-255] gmat + fp16 convert + h  |  [256+] scatter ----------------
__global__ void k_prep_scatter(const float* __restrict__ emb, const float* __restrict__ W,
                               const float* __restrict__ pb, const float* __restrict__ x,
                               const int* __restrict__ ids, const int* __restrict__ slen) {
    __shared__ float Ws[CC * CC];
    __shared__ float Es[16 * CC];
    __shared__ float pbs[CC];
    int t = threadIdx.x;
    if (blockIdx.x >= 256) {
        // ---- masked scatter-add ----
        int g = (blockIdx.x - 256) * 256 + t;
        if (g >= BB * SS * II * CC) return;
        int c = g & (CC - 1);
        int e = g >> 6;
        int bs = e / II;
        int s = bs % SS;
        int b = bs / SS;
        if (s < slen[b]) {
            int id = ids[e];
            atomicAdd(&g_sums[(((size_t)b * NN + id) << 6) + c], x[g]);
            if (c == 0) atomicAdd(&g_counts[b * NN + id], 1);
        }
        return;
    }
    {
        const float4* W4 = reinterpret_cast<const float4*>(W);
        float4* Ws4 = reinterpret_cast<float4*>(Ws);
        for (int k = t; k < 1024; k += 256) Ws4[k] = W4[k];
        const float4* E4 = reinterpret_cast<const float4*>(emb + (size_t)blockIdx.x * 16 * CC);
        reinterpret_cast<float4*>(Es)[t] = E4[t];
        if (t < CC) pbs[t] = pb[t];
    }
    __syncthreads();
    int nbase = blockIdx.x * 16;
    int c = t & (CC - 1);
    int rg = t >> 6;
#pragma unroll
    for (int it = 0; it < 4; it++) {
        int r = it * 4 + rg;
        float a0 = 0.0f, a1 = 0.0f;
#pragma unroll
        for (int cp = 0; cp < CC; cp += 2) {
            a0 = fmaf(Es[r * CC + cp],     Ws[cp * CC + c],       a0);
            a1 = fmaf(Es[r * CC + cp + 1], Ws[(cp + 1) * CC + c], a1);
        }
        float gv = a0 + a1;
        float ev = Es[r * CC + c];
        int si = swz(nbase + r, c);
        __half gh = __float2half(gv);
        g_eh[si] = __float2half(ev);
        g_gh[si] = gh;
        g_gl[si] = __float2half(gv - __half2float(gh));
    }
    if (t < 16) {
        float h = 0.0f;
#pragma unroll
        for (int cc = 0; cc < CC; cc++) h = fmaf(Es[t * CC + cc], pbs[cc], h);
        g_h[nbase + t] = h;
    }
}

// ---------------- K2a: slot assignment; writes inverse map slot -> (id|cnt<<12) ----------------
__global__ void k_slots() {
    __shared__ int wsum[32];
    int b = blockIdx.x;
    int t = threadIdx.x;          // 1024 threads, 4 ids each
    int base = b * NN;
    int cnts[4], flags[4];
    int local = 0;
#pragma unroll
    for (int j = 0; j < 4; j++) {
        cnts[j] = g_counts[base + t * 4 + j];
        flags[j] = (cnts[j] > 0);
        local += flags[j];
    }
    int lane = t & 31, wid = t >> 5;
    int v = local;
#pragma unroll
    for (int off = 1; off < 32; off <<= 1) {
        int u = __shfl_up_sync(0xffffffffu, v, off);
        if (lane >= off) v += u;
    }
    if (lane == 31) wsum[wid] = v;
    __syncthreads();
    if (wid == 0) {
        int w = wsum[lane];
#pragma unroll
        for (int off = 1; off < 32; off <<= 1) {
            int u = __shfl_up_sync(0xffffffffu, w, off);
            if (lane >= off) w += u;
        }
        wsum[lane] = w;
    }
    __syncthreads();
    int warpBase = (wid == 0) ? 0 : wsum[wid - 1];
    int excl = warpBase + v - local;
#pragma unroll
    for (int j = 0; j < 4; j++) {
        if (flags[j]) g_inv[b * MAXM + (excl++)] = (t * 4 + j) | (cnts[j] << 12);
    }
    if (t == 0) g_M[b] = wsum[31];
}

// ---------------- K2b: warp-per-slot: mean + fp16 convert + re-zero ----------------
__global__ void k_rowcvt() {
    int w = blockIdx.x * 8 + (threadIdx.x >> 5);   // slot index over BB*MAXM
    int lane = threadIdx.x & 31;
    int b = w >> 10;
    int slot = w & (MAXM - 1);
    if (slot >= g_M[b]) return;
    int packed = g_inv[w];
    int id = packed & 4095;
    float inv = 1.0f / (float)(packed >> 12);
    int src = b * NN + id;
    float2* srow = reinterpret_cast<float2*>(g_sums + ((size_t)src << 6));
    float2 v = srow[lane];
    __half h0 = __float2half(v.x * inv);
    __half h1 = __float2half(v.y * inv);
    uint32_t hp = (uint32_t)__half_as_ushort(h0) | ((uint32_t)__half_as_ushort(h1) << 16);
    int row = b * MAXM + slot;
    int ui = row * 32 + (((lane * 2) ^ ((row & 7) << 3)) >> 1);
    reinterpret_cast<uint32_t*>(g_ch)[ui] = hp;
    srow[lane] = make_float2(0.0f, 0.0f);          // restore invariant
    if (lane == 0) g_counts[src] = 0;
}

// ---------------- K3: tile kernel, (mc=256m, b, nt), 4 subtiles, 3-deep pipeline ----------------
// smem: 0 EH | 8192 GH | 16384 GL | 24576 + buf*8192: CH  (3 bufs)
#define SM_CBUF 24576
#define SM_TOTAL (24576 + 3 * 8192)

__device__ __forceinline__ void cp_csub(uint32_t sb, int b, int m0, int buf, int t, int M) {
    int mE = min(64, M - m0);
    int cnt = mE * 8;
    size_t g = ((size_t)(b * MAXM + m0)) * 8;
    const uint4* sh = reinterpret_cast<const uint4*>(g_ch) + g;
    uint32_t dst = sb + SM_CBUF + buf * 8192;
    for (int k = t; k < cnt; k += 256) CPA(dst + k * 16, sh + k);
}

__global__ void __launch_bounds__(256, 2) k_mma() {
    extern __shared__ __align__(1024) char smem[];
    int t = threadIdx.x;
    int bid = blockIdx.x;
    int nt = bid & 63;
    int b  = (bid >> 6) & 7;
    int mc = bid >> 9;
    int M = g_M[b];
    int m0 = mc * 256;
    if (m0 >= M) return;
    int nsub = min(4, (M - m0 + 63) >> 6);
    uint32_t sb = smem_u32(smem);

    // ---- group0: A (eh/gh/gl) + C0; group1: C1 ----
    {
        int arow = nt * 512;                       // uint4 offset: 64 rows * 8
        const uint4* s_eh = reinterpret_cast<const uint4*>(g_eh) + arow;
        const uint4* s_gh = reinterpret_cast<const uint4*>(g_gh) + arow;
        const uint4* s_gl = reinterpret_cast<const uint4*>(g_gl) + arow;
        for (int k = t; k < 512; k += 256) {
            CPA(sb + k * 16,         s_eh + k);
            CPA(sb + 8192 + k * 16,  s_gh + k);
            CPA(sb + 16384 + k * 16, s_gl + k);
        }
    }
    cp_csub(sb, b, m0, 0, t, M);
    CPCOMMIT();
    if (nsub > 1) { cp_csub(sb, b, m0 + 64, 1, t, M); CPCOMMIT(); }

    int lane = t & 31, wid = t >> 5;
    int wn = wid & 3, wm = wid >> 2;
    int mat = lane >> 3, rw = lane & 7;

    int rowA = wn * 16 + ((mat & 1) << 3) + rw;
    uint32_t xA = (uint32_t)(rowA * 128 + ((rowA & 7) << 4));
    int cgA = mat >> 1;
    int rowB = wm * 32 + ((mat >> 1) << 3) + rw;
    uint32_t xB0 = (uint32_t)(rowB * 128 + ((rowB & 7) << 4));
    uint32_t xB1 = xB0 + 16 * 128;
    int cgB = mat & 1;

    // ---- wait for A (group0), hoist all A fragments into registers ----
    if (nsub > 1) { CPWAIT(1); } else { CPWAIT(0); }
    __syncthreads();
    uint32_t AEH[4][4], AGH[4][4], AGL[4][4];
#pragma unroll
    for (int k16 = 0; k16 < 4; k16++) {
        uint32_t cA = (uint32_t)((2 * k16 + cgA) << 4);
        ldm4(AEH[k16], sb + 0     + (xA ^ cA));
        ldm4(AGH[k16], sb + 8192  + (xA ^ cA));
        ldm4(AGL[k16], sb + 16384 + (xA ^ cA));
    }

    float l1 = 0.0f, v1 = 0.0f, l2 = 0.0f, v2 = 0.0f;

#pragma unroll 1
    for (int s = 0; s < nsub; s++) {
        if (s + 2 < nsub) { cp_csub(sb, b, m0 + (s + 2) * 64, (s + 2) % 3, t, M); CPCOMMIT(); }
        int rem = nsub - 1 - s;
        if (rem >= 2) { CPWAIT(2); } else if (rem == 1) { CPWAIT(1); } else { CPWAIT(0); }
        __syncthreads();

        uint32_t cb = sb + SM_CBUF + (s % 3) * 8192;
        float aS[4][4], aT[4][4];
#pragma unroll
        for (int f = 0; f < 4; f++)
#pragma unroll
            for (int j = 0; j < 4; j++) { aS[f][j] = 0.0f; aT[f][j] = 0.0f; }

#pragma unroll
        for (int k16 = 0; k16 < 4; k16++) {
            uint32_t cB = (uint32_t)((2 * k16 + cgB) << 4);
#pragma unroll
            for (int g2 = 0; g2 < 2; g2++) {
                uint32_t xb = (g2 ? xB1 : xB0);
                uint32_t bh[4];
                ldm4(bh, cb + (xb ^ cB));
                // S = eh*ch ; T = gh*ch + gl*ch   (c-residual terms dropped: ~2e-4)
                mma16816(aS[2 * g2],     AEH[k16], bh[0], bh[1]);
                mma16816(aS[2 * g2 + 1], AEH[k16], bh[2], bh[3]);
                mma16816(aT[2 * g2],     AGH[k16], bh[0], bh[1]);
                mma16816(aT[2 * g2 + 1], AGH[k16], bh[2], bh[3]);
                mma16816(aT[2 * g2],     AGL[k16], bh[0], bh[1]);
                mma16816(aT[2 * g2 + 1], AGL[k16], bh[2], bh[3]);
            }
        }

        int mEnd = min(64, M - (m0 + s * 64));
#pragma unroll
        for (int f = 0; f < 4; f++) {
            int mloc = wm * 32 + f * 8 + ((lane & 3) << 1);
#pragma unroll
            for (int j = 0; j < 2; j++) {
                if (mloc + j < mEnd) {
                    float sc = aS[f][j];
                    sc = fmaxf(sc, 0.0f) + 0.2f * fminf(sc, 0.0f);
                    float e = __expf(sc);
                    l1 += e; v1 = fmaf(e, aT[f][j], v1);
                    float s2 = aS[f][j + 2];
                    s2 = fmaxf(s2, 0.0f) + 0.2f * fminf(s2, 0.0f);
                    float e2 = __expf(s2);
                    l2 += e2; v2 = fmaf(e2, aT[f][j + 2], v2);
                }
            }
        }
        if (s + 1 < nsub) __syncthreads();
    }

    // ---- reduce within quad, write per-(mc,wm) partial directly ----
#pragma unroll
    for (int off = 1; off < 4; off <<= 1) {
        l1 += __shfl_xor_sync(0xffffffffu, l1, off);
        v1 += __shfl_xor_sync(0xffffffffu, v1, off);
        l2 += __shfl_xor_sync(0xffffffffu, l2, off);
        v2 += __shfl_xor_sync(0xffffffffu, v2, off);
    }
    if ((lane & 3) == 0) {
        int n0 = nt * 64 + wn * 16 + (lane >> 2);
        size_t base = ((size_t)(mc * 2 + wm) * BB + b) * NN + n0;
        g_part[base]     = make_float2(l1, v1);
        g_part[base + 8] = make_float2(l2, v2);
    }
}

// ---------------- K4: finalize: sum valid (mc, wm) partials ----------------
__global__ void k_final(float* __restrict__ out) {
    int i = blockIdx.x * 256 + threadIdx.x;        // i = b*NN + n
    int b = i >> 12;
    int n = i & (NN - 1);
    int nh = ((g_M[b] + 255) >> 8) * 2;            // 2 wm halves per 256-m chunk
    float l = 0.0f, v = 0.0f;
    for (int h = 0; h < nh; h++) {
        float2 p = g_part[((size_t)h * BB + b) * NN + n];
        l += p.x; v += p.y;
    }
    out[i] = v / l + g_h[n];
}

extern "C" void kernel_launch(void* const* d_in, const int* in_sizes, int n_in,
                              void* d_out, int out_size) {
    const float* x    = (const float*)d_in[0];
    const float* emb  = (const float*)d_in[1];
    const float* W    = (const float*)d_in[2];
    const float* pb   = (const float*)d_in[3];
    const int*   ids  = (const int*)d_in[4];
    const int*   slen = (const int*)d_in[5];
    float* out = (float*)d_out;

    cudaFuncSetAttribute(k_mma, cudaFuncAttributeMaxDynamicSharedMemorySize, SM_TOTAL);

    int scat_blocks = (BB * SS * II * CC + 255) / 256;
    k_prep_scatter<<<256 + scat_blocks, 256>>>(emb, W, pb, x, ids, slen);
    k_slots<<<BB, 1024>>>();
    k_rowcvt<<<BB * MAXM / 8, 256>>>();
    k_mma<<<4 * BB * 64, 256, SM_TOTAL>>>();
    k_final<<<(BB * NN) / 256, 256>>>(out);
}